// round 12
// baseline (speedup 1.0000x reference)
#include <cuda_runtime.h>
#include <cuda_bf16.h>
#include <cstdint>

#define BATCH 8
#define TE    256
#define TD    128
#define HE    512
#define HC    16
#define DT    8

#define MROWS (BATCH * TE + BATCH * TD)   // 3072 combined A rows
#define MT_WS (BATCH * TE / 128)          // 16 m-tiles for Ws

// ---------------- scratch ----------------
__device__ float g_Ws[BATCH * TE * HE];                     // tanh(enc @ W_a)
__device__ float g_Uh[BATCH * TD * HE];                     // tanh(dec @ U_a)
__device__ float g_E [BATCH * TD * TE];                     // raw logits
__device__ __align__(16) __nv_bfloat16 g_Ah[MROWS * HE];
__device__ __align__(16) __nv_bfloat16 g_Al[MROWS * HE];
__device__ __align__(16) __nv_bfloat16 g_Bh[2 * HE * HE];
__device__ __align__(16) __nv_bfloat16 g_Bl[2 * HE * HE];

__device__ __forceinline__ float fast_tanh(float x) {
    float y;
    asm("tanh.approx.f32 %0, %1;" : "=f"(y) : "f"(x));
    return y;
}
__device__ __forceinline__ float fast_rcp(float x) {
    float y;
    asm("rcp.approx.f32 %0, %1;" : "=f"(y) : "f"(x));
    return y;
}
__device__ __forceinline__ uint32_t smem_u32(const void* p) {
    uint32_t a;
    asm("{ .reg .u64 t; cvta.to.shared.u64 t, %1; cvt.u32.u64 %0, t; }" : "=r"(a) : "l"(p));
    return a;
}
__device__ __forceinline__ void cp16(uint32_t dst, const void* src) {
    asm volatile("cp.async.cg.shared.global [%0], [%1], 16;" :: "r"(dst), "l"(src));
}
__device__ __forceinline__ void mma_bf16(float* c, const uint32_t* a, const uint32_t* b) {
    asm volatile(
        "mma.sync.aligned.m16n8k16.row.col.f32.bf16.bf16.f32 "
        "{%0,%1,%2,%3}, {%4,%5,%6,%7}, {%8,%9}, {%0,%1,%2,%3};"
        : "+f"(c[0]), "+f"(c[1]), "+f"(c[2]), "+f"(c[3])
        : "r"(a[0]), "r"(a[1]), "r"(a[2]), "r"(a[3]), "r"(b[0]), "r"(b[1]));
}

// ================= merged conversion kernel =================
#define CONV_A_BLOCKS (MROWS * HE / 4 / 512)     // 768
__global__ __launch_bounds__(512) void conv_all(const float* __restrict__ enc,
                                                const float* __restrict__ dec,
                                                const float* __restrict__ W,
                                                const float* __restrict__ U) {
    const int tid = threadIdx.x;
    if (blockIdx.x < CONV_A_BLOCKS) {
        int i = blockIdx.x * 512 + tid;
        int row = i / (HE / 4), q = i % (HE / 4);
        const float* src = row < BATCH * TE ? enc + row * HE
                                            : dec + (row - BATCH * TE) * HE;
        float4 v = *(const float4*)(src + 4 * q);
        float vv[4] = {v.x, v.y, v.z, v.w};
        __nv_bfloat16 h[4], l[4];
        #pragma unroll
        for (int j = 0; j < 4; j++) {
            h[j] = __float2bfloat16(vv[j]);
            l[j] = __float2bfloat16(vv[j] - __bfloat162float(h[j]));
        }
        *(uint64_t*)&g_Ah[i * 4] = *(uint64_t*)h;
        *(uint64_t*)&g_Al[i * 4] = *(uint64_t*)l;
    } else {
        __shared__ float t[32][33];
        int bb = blockIdx.x - CONV_A_BLOCKS;       // 0..511
        int z   = bb >> 8;                         // 0=W, 1=U
        int rem = bb & 255;
        int n0 = (rem & 15) * 32, k0 = (rem >> 4) * 32;
        const float* S = z ? U : W;
        int tx = tid & 31, ty = tid >> 5;          // (32,16)
        #pragma unroll
        for (int i = 0; i < 2; i++) {
            int r = ty + 16 * i;
            t[r][tx] = S[(k0 + r) * HE + n0 + tx];
        }
        __syncthreads();
        #pragma unroll
        for (int i = 0; i < 2; i++) {
            int n = ty + 16 * i;
            float v = t[tx][n];
            __nv_bfloat16 h = __float2bfloat16(v);
            __nv_bfloat16 l = __float2bfloat16(v - __bfloat162float(h));
            size_t o = (size_t)(z * HE + n0 + n) * HE + k0 + tx;
            g_Bh[o] = h;
            g_Bl[o] = l;
        }
    }
}

// ================= HMMA GEMM: 128x32 C tiles, 384 CTAs, tanh epilogue ============
#define BN       32
#define TA_B     (128 * 80)                  // 10240
#define TB_B     (BN * 80)                   //  2560
#define OFF_AH   0
#define OFF_AL   TA_B
#define OFF_BH   (2 * TA_B)
#define OFF_BL   (2 * TA_B + TB_B)
#define STAGEB   (2 * TA_B + 2 * TB_B)       // 25600
#define GEMM_SMEM (2 * STAGEB)               // 51200

__global__ __launch_bounds__(256) void gemm_tc() {
    extern __shared__ char smem[];
    const uint32_t sb = smem_u32(smem);
    const int tid = threadIdx.x;
    const int w = tid >> 5, lane = tid & 31;
    const int gid = lane >> 2, tig = lane & 3;
    const int mt = blockIdx.y, nt = blockIdx.x;      // mt 0..23, nt 0..15
    const int m0 = (mt < MT_WS ? mt : mt - MT_WS) * 128;
    const int aB = (mt < MT_WS ? 0 : BATCH * TE);
    const int bB = (mt < MT_WS ? 0 : HE);
    float* C = (mt < MT_WS ? g_Ws : g_Uh);
    const int n0 = nt * BN;
    const int wm = (w >> 1) * 32;            // 0,32,64,96
    const int wn = (w & 1) * 16;             // 0,16

    const int s_row0 = tid >> 2, s_q = tid & 3;               // 64 rows x 4 quads
    const uint32_t s_so0 = (uint32_t)(s_row0 * 80 + s_q * 16);

    float acc[2][2][4] = {};

    auto stage = [&](int c, int s) {
        uint32_t base = sb + s * STAGEB;
        #pragma unroll
        for (int t = 0; t < 2; t++) {
            uint32_t so = s_so0 + t * 64 * 80;
            size_t ga = (size_t)(aB + m0 + s_row0 + 64 * t) * HE + c * 32 + s_q * 8;
            cp16(base + OFF_AH + so, g_Ah + ga);
            cp16(base + OFF_AL + so, g_Al + ga);
        }
        if (s_row0 < BN) {
            size_t gb = (size_t)(bB + n0 + s_row0) * HE + c * 32 + s_q * 8;
            cp16(base + OFF_BH + s_so0, g_Bh + gb);
            cp16(base + OFF_BL + s_so0, g_Bl + gb);
        }
        asm volatile("cp.async.commit_group;" ::: "memory");
    };

    stage(0, 0);

    for (int c = 0; c < HE / 32; c++) {
        const int s = c & 1;
        if (c + 1 < HE / 32) {
            stage(c + 1, s ^ 1);
            asm volatile("cp.async.wait_group 1;" ::: "memory");
        } else {
            asm volatile("cp.async.wait_group 0;" ::: "memory");
        }
        __syncthreads();

        const char* tAh = smem + s * STAGEB + OFF_AH;
        const char* tAl = smem + s * STAGEB + OFF_AL;
        const char* tBh = smem + s * STAGEB + OFF_BH;
        const char* tBl = smem + s * STAGEB + OFF_BL;

        #pragma unroll
        for (int ks = 0; ks < 2; ks++) {
            const uint32_t kb = ks * 32 + 4 * tig;
            uint32_t aH[2][4], aL[2][4], bH[2][2], bL[2][2];
            #pragma unroll
            for (int mi = 0; mi < 2; mi++) {
                uint32_t ra = (uint32_t)((wm + mi * 16 + gid) * 80) + kb;
                aH[mi][0] = *(const uint32_t*)(tAh + ra);
                aH[mi][1] = *(const uint32_t*)(tAh + ra + 8 * 80);
                aH[mi][2] = *(const uint32_t*)(tAh + ra + 16);
                aH[mi][3] = *(const uint32_t*)(tAh + ra + 8 * 80 + 16);
                aL[mi][0] = *(const uint32_t*)(tAl + ra);
                aL[mi][1] = *(const uint32_t*)(tAl + ra + 8 * 80);
                aL[mi][2] = *(const uint32_t*)(tAl + ra + 16);
                aL[mi][3] = *(const uint32_t*)(tAl + ra + 8 * 80 + 16);
            }
            #pragma unroll
            for (int ni = 0; ni < 2; ni++) {
                uint32_t rb = (uint32_t)((wn + ni * 8 + gid) * 80) + kb;
                bH[ni][0] = *(const uint32_t*)(tBh + rb);
                bH[ni][1] = *(const uint32_t*)(tBh + rb + 16);
                bL[ni][0] = *(const uint32_t*)(tBl + rb);
                bL[ni][1] = *(const uint32_t*)(tBl + rb + 16);
            }
            #pragma unroll
            for (int mi = 0; mi < 2; mi++)
                #pragma unroll
                for (int ni = 0; ni < 2; ni++) {
                    mma_bf16(acc[mi][ni], aH[mi], bH[ni]);
                    mma_bf16(acc[mi][ni], aL[mi], bH[ni]);
                    mma_bf16(acc[mi][ni], aH[mi], bL[ni]);
                }
        }
        __syncthreads();
    }

    // epilogue: store tanh of the projection (enables the addition identity)
    const int er = gid, ec = 2 * tig;
    #pragma unroll
    for (int mi = 0; mi < 2; mi++)
        #pragma unroll
        for (int ni = 0; ni < 2; ni++) {
            int row = m0 + wm + mi * 16 + er;
            int col = n0 + wn + ni * 8 + ec;
            *(float2*)&C[(size_t)row * HE + col] =
                make_float2(fast_tanh(acc[mi][ni][0]), fast_tanh(acc[mi][ni][1]));
            *(float2*)&C[(size_t)(row + 8) * HE + col] =
                make_float2(fast_tanh(acc[mi][ni][2]), fast_tanh(acc[mi][ni][3]));
        }
}

// ================= e-compute via tanh addition identity (MUFU.RCP-bound) =========
// e[d,t] = sum_h V[h]*(ta+tb)/(1+ta*tb);  ta,tb pre-tanh'd by gemm epilogue.
// All smem STATIC (round-8 regression was dynamic-smem ALU overhead).
__global__ __launch_bounds__(512) void e_comp(const float* __restrict__ V) {
    __shared__ float tile[2][HC][128 + 1];   // 16512 B
    __shared__ float sV[HE];                 //  2048 B
    __shared__ float sU[DT * HE];            // 16384 B  (34944 static)

    const int tid = threadIdx.x;
    const int th = blockIdx.x;
    const int dg = blockIdx.y;
    const int b  = blockIdx.z;
    const int d0 = dg * DT;
    const int t  = tid & 127;
    const int dq = tid >> 7;

    for (int i = tid; i < HE; i += 512) sV[i] = V[i];
    for (int i = tid; i < DT * HE; i += 512)
        sU[i] = g_Uh[(b * TD + d0) * HE + i];            // = tanh(Uh)
    const float* wsb = g_Ws + (size_t)(b * TE + th * 128) * HE;   // = tanh(Ws)

    #pragma unroll
    for (int k = 0; k < 4; k++) {
        int i = tid + k * 512;
        int hh = i & (HC - 1), tt = i >> 4;
        tile[0][hh][tt] = wsb[tt * HE + hh];
    }
    __syncthreads();

    float e_acc[2] = {};
    float pre[4];

    for (int c = 0; c < HE / HC; c++) {
        const int buf = c & 1;
        if (c + 1 < HE / HC) {
            #pragma unroll
            for (int k = 0; k < 4; k++) {
                int i = tid + k * 512;
                int hh = i & (HC - 1), tt = i >> 4;
                pre[k] = wsb[tt * HE + (c + 1) * HC + hh];
            }
        }
        #pragma unroll
        for (int jj = 0; jj < HC; jj++) {
            float ta = tile[buf][jj][t];                  // conflict-free
            float vj = sV[c * HC + jj];                   // broadcast
            #pragma unroll
            for (int dd = 0; dd < 2; dd++) {
                float tb  = sU[(dq * 2 + dd) * HE + c * HC + jj];  // broadcast
                float s   = ta + tb;
                float den = fmaf(ta, tb, 1.0f);
                e_acc[dd] = fmaf(vj * s, fast_rcp(den), e_acc[dd]);
            }
        }
        if (c + 1 < HE / HC) {
            #pragma unroll
            for (int k = 0; k < 4; k++) {
                int i = tid + k * 512;
                int hh = i & (HC - 1), tt = i >> 4;
                tile[buf ^ 1][hh][tt] = pre[k];
            }
        }
        __syncthreads();
    }

    #pragma unroll
    for (int dd = 0; dd < 2; dd++)
        g_E[(size_t)(b * TD + d0 + dq * 2 + dd) * TE + th * 128 + t] = e_acc[dd];
}

// ================= fused softmax + context: h-quarters, 512 blocks ==============
// grid (hq=4, dg=16, b=8), 512 threads: hp = tid&63 (float2 in h-quarter),
// th = tid>>6 in 0..7 -> 32 t-iterations each, 7-partial smem reduction.
__global__ __launch_bounds__(512) void ctx_kernel(const float* __restrict__ enc,
                                                  float* __restrict__ outE,
                                                  float* __restrict__ outC) {
    __shared__ float  sE[DT][TE];            //  8 KB
    __shared__ float2 red2[7][DT][64];       // 28 KB

    const int tid = threadIdx.x;
    const int hq = blockIdx.x;               // h-quarter
    const int dg = blockIdx.y;
    const int b  = blockIdx.z;
    const int d0 = dg * DT;

    for (int i = tid; i < DT * TE; i += 512)
        ((float*)sE)[i] = g_E[(size_t)(b * TD + d0) * TE + i];
    __syncthreads();

    // softmax: warp w (0..7) handles d = w
    {
        const int w = tid >> 5, lane = tid & 31;
        if (w < DT) {
            float vals[8];
            float m = -1e30f;
            #pragma unroll
            for (int i = 0; i < 8; i++) {
                vals[i] = sE[w][lane + 32 * i];
                m = fmaxf(m, vals[i]);
            }
            #pragma unroll
            for (int o = 16; o; o >>= 1) m = fmaxf(m, __shfl_xor_sync(0xffffffffu, m, o));
            float s = 0.f;
            #pragma unroll
            for (int i = 0; i < 8; i++) { vals[i] = __expf(vals[i] - m); s += vals[i]; }
            #pragma unroll
            for (int o = 16; o; o >>= 1) s += __shfl_xor_sync(0xffffffffu, s, o);
            float inv = 1.0f / s;
            float* oe = outE + (size_t)(b * TD + d0 + w) * TE;
            #pragma unroll
            for (int i = 0; i < 8; i++) {
                float ef = vals[i] * inv;
                sE[w][lane + 32 * i] = ef;
                if (hq == 0) oe[lane + 32 * i] = ef;
            }
        }
    }
    __syncthreads();

    const int hp = tid & 63;
    const int th = tid >> 6;                 // 0..7, each handles 32 t
    const float2* enc2 = (const float2*)(enc + (size_t)b * TE * HE);

    float2 acc[DT];
    #pragma unroll
    for (int d = 0; d < DT; d++) acc[d] = make_float2(0.f, 0.f);

    #pragma unroll 4
    for (int tt = 0; tt < TE / 8; tt++) {
        int t = th * (TE / 8) + tt;
        float2 v2 = enc2[t * (HE / 2) + hq * 64 + hp];
        #pragma unroll
        for (int d = 0; d < DT; d++) {
            float e = sE[d][t];
            acc[d].x = fmaf(e, v2.x, acc[d].x);
            acc[d].y = fmaf(e, v2.y, acc[d].y);
        }
    }

    if (th > 0) {
        #pragma unroll
        for (int d = 0; d < DT; d++) red2[th - 1][d][hp] = acc[d];
    }
    __syncthreads();
    if (th == 0) {
        #pragma unroll
        for (int d = 0; d < DT; d++) {
            float2 o = acc[d];
            #pragma unroll
            for (int p = 0; p < 7; p++) {
                float2 q = red2[p][d][hp];
                o.x += q.x;  o.y += q.y;
            }
            ((float2*)(outC + (size_t)(b * TD + d0 + d) * HE))[hq * 64 + hp] = o;
        }
    }
}

// ================= launch =================
extern "C" void kernel_launch(void* const* d_in, const int* in_sizes, int n_in,
                              void* d_out, int out_size) {
    const float* enc = (const float*)d_in[0];
    const float* dec = (const float*)d_in[1];
    const float* W_a = (const float*)d_in[2];
    const float* U_a = (const float*)d_in[3];
    const float* V_a = (const float*)d_in[4];

    float* outC = (float*)d_out;
    float* outE = (float*)d_out + BATCH * TD * HE;

    cudaFuncSetAttribute(gemm_tc, cudaFuncAttributeMaxDynamicSharedMemorySize, GEMM_SMEM);

    conv_all<<<CONV_A_BLOCKS + 512, 512>>>(enc, dec, W_a, U_a);
    gemm_tc<<<dim3(HE / BN, MROWS / 128), 256, GEMM_SMEM>>>();
    e_comp<<<dim3(2, TD / DT, BATCH), 512>>>(V_a);
    ctx_kernel<<<dim3(4, TD / DT, BATCH), 512>>>(enc, outE, outC);
}

// round 13
// speedup vs baseline: 2.0988x; 2.0988x over previous
#include <cuda_runtime.h>
#include <cuda_bf16.h>
#include <cstdint>

#define BATCH 8
#define TE    256
#define TD    128
#define HE    512
#define HC    16
#define DT    8

#define MROWS (BATCH * TE + BATCH * TD)   // 3072 combined A rows
#define MT_WS (BATCH * TE / 128)          // 16 m-tiles for Ws

// ---------------- scratch ----------------
__device__ float g_Ws[BATCH * TE * HE];                     // enc @ W_a (raw)
__device__ float g_Uh[BATCH * TD * HE];                     // dec @ U_a (raw)
__device__ float g_E [BATCH * TD * TE];                     // raw logits
__device__ __align__(16) __nv_bfloat16 g_Ah[MROWS * HE];
__device__ __align__(16) __nv_bfloat16 g_Al[MROWS * HE];
__device__ __align__(16) __nv_bfloat16 g_Bh[2 * HE * HE];
__device__ __align__(16) __nv_bfloat16 g_Bl[2 * HE * HE];

__device__ __forceinline__ float fast_tanh(float x) {
    float y;
    asm("tanh.approx.f32 %0, %1;" : "=f"(y) : "f"(x));
    return y;
}
__device__ __forceinline__ uint32_t smem_u32(const void* p) {
    uint32_t a;
    asm("{ .reg .u64 t; cvta.to.shared.u64 t, %1; cvt.u32.u64 %0, t; }" : "=r"(a) : "l"(p));
    return a;
}
__device__ __forceinline__ void cp16(uint32_t dst, const void* src) {
    asm volatile("cp.async.cg.shared.global [%0], [%1], 16;" :: "r"(dst), "l"(src));
}
__device__ __forceinline__ void mma_bf16(float* c, const uint32_t* a, const uint32_t* b) {
    asm volatile(
        "mma.sync.aligned.m16n8k16.row.col.f32.bf16.bf16.f32 "
        "{%0,%1,%2,%3}, {%4,%5,%6,%7}, {%8,%9}, {%0,%1,%2,%3};"
        : "+f"(c[0]), "+f"(c[1]), "+f"(c[2]), "+f"(c[3])
        : "r"(a[0]), "r"(a[1]), "r"(a[2]), "r"(a[3]), "r"(b[0]), "r"(b[1]));
}

// ================= merged conversion kernel =================
#define CONV_A_BLOCKS (MROWS * HE / 4 / 512)     // 768
__global__ __launch_bounds__(512) void conv_all(const float* __restrict__ enc,
                                                const float* __restrict__ dec,
                                                const float* __restrict__ W,
                                                const float* __restrict__ U) {
    const int tid = threadIdx.x;
    if (blockIdx.x < CONV_A_BLOCKS) {
        int i = blockIdx.x * 512 + tid;
        int row = i / (HE / 4), q = i % (HE / 4);
        const float* src = row < BATCH * TE ? enc + row * HE
                                            : dec + (row - BATCH * TE) * HE;
        float4 v = *(const float4*)(src + 4 * q);
        float vv[4] = {v.x, v.y, v.z, v.w};
        __nv_bfloat16 h[4], l[4];
        #pragma unroll
        for (int j = 0; j < 4; j++) {
            h[j] = __float2bfloat16(vv[j]);
            l[j] = __float2bfloat16(vv[j] - __bfloat162float(h[j]));
        }
        *(uint64_t*)&g_Ah[i * 4] = *(uint64_t*)h;
        *(uint64_t*)&g_Al[i * 4] = *(uint64_t*)l;
    } else {
        __shared__ float t[32][33];
        int bb = blockIdx.x - CONV_A_BLOCKS;       // 0..511
        int z   = bb >> 8;                         // 0=W, 1=U
        int rem = bb & 255;
        int n0 = (rem & 15) * 32, k0 = (rem >> 4) * 32;
        const float* S = z ? U : W;
        int tx = tid & 31, ty = tid >> 5;          // (32,16)
        #pragma unroll
        for (int i = 0; i < 2; i++) {
            int r = ty + 16 * i;
            t[r][tx] = S[(k0 + r) * HE + n0 + tx];
        }
        __syncthreads();
        #pragma unroll
        for (int i = 0; i < 2; i++) {
            int n = ty + 16 * i;
            float v = t[tx][n];
            __nv_bfloat16 h = __float2bfloat16(v);
            __nv_bfloat16 l = __float2bfloat16(v - __bfloat162float(h));
            size_t o = (size_t)(z * HE + n0 + n) * HE + k0 + tx;
            g_Bh[o] = h;
            g_Bl[o] = l;
        }
    }
}

// ================= HMMA GEMM: 128x32 C tiles, 384 CTAs =================
#define BN       32
#define TA_B     (128 * 80)                  // 10240
#define TB_B     (BN * 80)                   //  2560
#define OFF_AH   0
#define OFF_AL   TA_B
#define OFF_BH   (2 * TA_B)
#define OFF_BL   (2 * TA_B + TB_B)
#define STAGEB   (2 * TA_B + 2 * TB_B)       // 25600
#define GEMM_SMEM (2 * STAGEB)               // 51200

__global__ __launch_bounds__(256) void gemm_tc() {
    extern __shared__ char smem[];
    const uint32_t sb = smem_u32(smem);
    const int tid = threadIdx.x;
    const int w = tid >> 5, lane = tid & 31;
    const int gid = lane >> 2, tig = lane & 3;
    const int mt = blockIdx.y, nt = blockIdx.x;      // mt 0..23, nt 0..15
    const int m0 = (mt < MT_WS ? mt : mt - MT_WS) * 128;
    const int aB = (mt < MT_WS ? 0 : BATCH * TE);
    const int bB = (mt < MT_WS ? 0 : HE);
    float* C = (mt < MT_WS ? g_Ws : g_Uh);
    const int n0 = nt * BN;
    const int wm = (w >> 1) * 32;            // 0,32,64,96
    const int wn = (w & 1) * 16;             // 0,16

    const int s_row0 = tid >> 2, s_q = tid & 3;               // 64 rows x 4 quads
    const uint32_t s_so0 = (uint32_t)(s_row0 * 80 + s_q * 16);

    float acc[2][2][4] = {};

    auto stage = [&](int c, int s) {
        uint32_t base = sb + s * STAGEB;
        #pragma unroll
        for (int t = 0; t < 2; t++) {
            uint32_t so = s_so0 + t * 64 * 80;
            size_t ga = (size_t)(aB + m0 + s_row0 + 64 * t) * HE + c * 32 + s_q * 8;
            cp16(base + OFF_AH + so, g_Ah + ga);
            cp16(base + OFF_AL + so, g_Al + ga);
        }
        if (s_row0 < BN) {
            size_t gb = (size_t)(bB + n0 + s_row0) * HE + c * 32 + s_q * 8;
            cp16(base + OFF_BH + s_so0, g_Bh + gb);
            cp16(base + OFF_BL + s_so0, g_Bl + gb);
        }
        asm volatile("cp.async.commit_group;" ::: "memory");
    };

    stage(0, 0);

    for (int c = 0; c < HE / 32; c++) {
        const int s = c & 1;
        if (c + 1 < HE / 32) {
            stage(c + 1, s ^ 1);
            asm volatile("cp.async.wait_group 1;" ::: "memory");
        } else {
            asm volatile("cp.async.wait_group 0;" ::: "memory");
        }
        __syncthreads();

        const char* tAh = smem + s * STAGEB + OFF_AH;
        const char* tAl = smem + s * STAGEB + OFF_AL;
        const char* tBh = smem + s * STAGEB + OFF_BH;
        const char* tBl = smem + s * STAGEB + OFF_BL;

        #pragma unroll
        for (int ks = 0; ks < 2; ks++) {
            const uint32_t kb = ks * 32 + 4 * tig;
            uint32_t aH[2][4], aL[2][4], bH[2][2], bL[2][2];
            #pragma unroll
            for (int mi = 0; mi < 2; mi++) {
                uint32_t ra = (uint32_t)((wm + mi * 16 + gid) * 80) + kb;
                aH[mi][0] = *(const uint32_t*)(tAh + ra);
                aH[mi][1] = *(const uint32_t*)(tAh + ra + 8 * 80);
                aH[mi][2] = *(const uint32_t*)(tAh + ra + 16);
                aH[mi][3] = *(const uint32_t*)(tAh + ra + 8 * 80 + 16);
                aL[mi][0] = *(const uint32_t*)(tAl + ra);
                aL[mi][1] = *(const uint32_t*)(tAl + ra + 8 * 80);
                aL[mi][2] = *(const uint32_t*)(tAl + ra + 16);
                aL[mi][3] = *(const uint32_t*)(tAl + ra + 8 * 80 + 16);
            }
            #pragma unroll
            for (int ni = 0; ni < 2; ni++) {
                uint32_t rb = (uint32_t)((wn + ni * 8 + gid) * 80) + kb;
                bH[ni][0] = *(const uint32_t*)(tBh + rb);
                bH[ni][1] = *(const uint32_t*)(tBh + rb + 16);
                bL[ni][0] = *(const uint32_t*)(tBl + rb);
                bL[ni][1] = *(const uint32_t*)(tBl + rb + 16);
            }
            #pragma unroll
            for (int mi = 0; mi < 2; mi++)
                #pragma unroll
                for (int ni = 0; ni < 2; ni++) {
                    mma_bf16(acc[mi][ni], aH[mi], bH[ni]);
                    mma_bf16(acc[mi][ni], aL[mi], bH[ni]);
                    mma_bf16(acc[mi][ni], aH[mi], bL[ni]);
                }
        }
        __syncthreads();
    }

    const int er = gid, ec = 2 * tig;
    #pragma unroll
    for (int mi = 0; mi < 2; mi++)
        #pragma unroll
        for (int ni = 0; ni < 2; ni++) {
            int row = m0 + wm + mi * 16 + er;
            int col = n0 + wn + ni * 8 + ec;
            *(float2*)&C[(size_t)row * HE + col] =
                make_float2(acc[mi][ni][0], acc[mi][ni][1]);
            *(float2*)&C[(size_t)(row + 8) * HE + col] =
                make_float2(acc[mi][ni][2], acc[mi][ni][3]);
        }
}

// ================= e-compute: raw logits -> g_E (MUFU.TANH floor) =================
__global__ __launch_bounds__(512) void e_comp(const float* __restrict__ V) {
    __shared__ float tile[2][HC][128 + 1];
    __shared__ float sV[HE];
    __shared__ float sU[DT * HE];

    const int tid = threadIdx.x;
    const int th = blockIdx.x;
    const int dg = blockIdx.y;
    const int b  = blockIdx.z;
    const int d0 = dg * DT;
    const int t  = tid & 127;
    const int dq = tid >> 7;

    for (int i = tid; i < HE; i += 512) sV[i] = V[i];
    for (int i = tid; i < DT * HE; i += 512)
        sU[i] = g_Uh[(b * TD + d0) * HE + i];
    const float* wsb = g_Ws + (size_t)(b * TE + th * 128) * HE;

    #pragma unroll
    for (int k = 0; k < 4; k++) {
        int i = tid + k * 512;
        int hh = i & (HC - 1), tt = i >> 4;
        tile[0][hh][tt] = wsb[tt * HE + hh];
    }
    __syncthreads();

    float e_acc[2] = {};
    float pre[4];

    for (int c = 0; c < HE / HC; c++) {
        const int buf = c & 1;
        if (c + 1 < HE / HC) {
            #pragma unroll
            for (int k = 0; k < 4; k++) {
                int i = tid + k * 512;
                int hh = i & (HC - 1), tt = i >> 4;
                pre[k] = wsb[tt * HE + (c + 1) * HC + hh];
            }
        }
        #pragma unroll
        for (int jj = 0; jj < HC; jj++) {
            float x = tile[buf][jj][t];
            float v = sV[c * HC + jj];
            #pragma unroll
            for (int dd = 0; dd < 2; dd++) {
                float u = sU[(dq * 2 + dd) * HE + c * HC + jj];
                e_acc[dd] = fmaf(v, fast_tanh(x + u), e_acc[dd]);
            }
        }
        if (c + 1 < HE / HC) {
            #pragma unroll
            for (int k = 0; k < 4; k++) {
                int i = tid + k * 512;
                int hh = i & (HC - 1), tt = i >> 4;
                tile[buf ^ 1][hh][tt] = pre[k];
            }
        }
        __syncthreads();
    }

    #pragma unroll
    for (int dd = 0; dd < 2; dd++)
        g_E[(size_t)(b * TD + d0 + dq * 2 + dd) * TE + th * 128 + t] = e_acc[dd];
}

// ================= fused softmax + context (round-11 shape, unroll 8) =============
// grid (hh=2, dg=16, b=8) = 256 blocks, 512 threads (16 warps).
__global__ __launch_bounds__(512) void ctx_kernel(const float* __restrict__ enc,
                                                  float* __restrict__ outE,
                                                  float* __restrict__ outC) {
    __shared__ float  sE[DT][TE];            //  8 KB
    __shared__ float2 red2[3][DT][128];      // 24 KB

    const int tid = threadIdx.x;
    const int hh = blockIdx.x;
    const int dg = blockIdx.y;
    const int b  = blockIdx.z;
    const int d0 = dg * DT;

    for (int i = tid; i < DT * TE; i += 512)
        ((float*)sE)[i] = g_E[(size_t)(b * TD + d0) * TE + i];
    __syncthreads();

    // softmax: warp w (0..7) handles d = w
    {
        const int w = tid >> 5, lane = tid & 31;
        if (w < DT) {
            float vals[8];
            float m = -1e30f;
            #pragma unroll
            for (int i = 0; i < 8; i++) {
                vals[i] = sE[w][lane + 32 * i];
                m = fmaxf(m, vals[i]);
            }
            #pragma unroll
            for (int o = 16; o; o >>= 1) m = fmaxf(m, __shfl_xor_sync(0xffffffffu, m, o));
            float s = 0.f;
            #pragma unroll
            for (int i = 0; i < 8; i++) { vals[i] = __expf(vals[i] - m); s += vals[i]; }
            #pragma unroll
            for (int o = 16; o; o >>= 1) s += __shfl_xor_sync(0xffffffffu, s, o);
            float inv = 1.0f / s;
            float* oe = outE + (size_t)(b * TD + d0 + w) * TE;
            #pragma unroll
            for (int i = 0; i < 8; i++) {
                float ef = vals[i] * inv;
                sE[w][lane + 32 * i] = ef;
                if (hh == 0) oe[lane + 32 * i] = ef;
            }
        }
    }
    __syncthreads();

    const int hp = tid & 127;
    const int th = tid >> 7;                 // 0..3, each handles 64 t
    const float2* enc2 = (const float2*)(enc + (size_t)b * TE * HE);

    float2 acc[DT];
    #pragma unroll
    for (int d = 0; d < DT; d++) acc[d] = make_float2(0.f, 0.f);

    #pragma unroll 8
    for (int tt = 0; tt < TE / 4; tt++) {
        int t = th * (TE / 4) + tt;
        float2 v2 = enc2[t * (HE / 2) + hh * 128 + hp];
        #pragma unroll
        for (int d = 0; d < DT; d++) {
            float e = sE[d][t];
            acc[d].x = fmaf(e, v2.x, acc[d].x);
            acc[d].y = fmaf(e, v2.y, acc[d].y);
        }
    }

    if (th > 0) {
        #pragma unroll
        for (int d = 0; d < DT; d++) red2[th - 1][d][hp] = acc[d];
    }
    __syncthreads();
    if (th == 0) {
        #pragma unroll
        for (int d = 0; d < DT; d++) {
            float2 p0 = red2[0][d][hp], p1 = red2[1][d][hp], p2 = red2[2][d][hp];
            float2 o;
            o.x = acc[d].x + p0.x + p1.x + p2.x;
            o.y = acc[d].y + p0.y + p1.y + p2.y;
            ((float2*)(outC + (size_t)(b * TD + d0 + d) * HE))[hh * 128 + hp] = o;
        }
    }
}

// ================= launch =================
extern "C" void kernel_launch(void* const* d_in, const int* in_sizes, int n_in,
                              void* d_out, int out_size) {
    const float* enc = (const float*)d_in[0];
    const float* dec = (const float*)d_in[1];
    const float* W_a = (const float*)d_in[2];
    const float* U_a = (const float*)d_in[3];
    const float* V_a = (const float*)d_in[4];

    float* outC = (float*)d_out;
    float* outE = (float*)d_out + BATCH * TD * HE;

    cudaFuncSetAttribute(gemm_tc, cudaFuncAttributeMaxDynamicSharedMemorySize, GEMM_SMEM);

    conv_all<<<CONV_A_BLOCKS + 512, 512>>>(enc, dec, W_a, U_a);
    gemm_tc<<<dim3(HE / BN, MROWS / 128), 256, GEMM_SMEM>>>();
    e_comp<<<dim3(2, TD / DT, BATCH), 512>>>(V_a);
    ctx_kernel<<<dim3(2, TD / DT, BATCH), 512>>>(enc, outE, outC);
}